// round 3
// baseline (speedup 1.0000x reference)
#include <cuda_runtime.h>

#define FDIM 64
#define NMAX 50176

// Scratch (allocation-free rule: __device__ globals)
__device__ __align__(16) float g_u[NMAX * FDIM];
__device__ __align__(16) float g_v[NMAX * FDIM];
__device__ __align__(16) float g_hs[NMAX * FDIM];
__device__ __align__(16) float g_hd[NMAX * FDIM];
__device__ __align__(16) float g_min[NMAX * FDIM];
__device__ __align__(16) float g_mout[NMAX * FDIM];
__device__ __align__(16) float g_ideg[NMAX];
__device__ __align__(16) float g_odeg[NMAX];

__device__ __forceinline__ void red2(float* p, float a, float b) {
    asm volatile("red.global.add.v2.f32 [%0], {%1, %2};"
                 :: "l"(__cvta_generic_to_global(p)), "f"(a), "f"(b)
                 : "memory");
}

// ---------------------------------------------------------------- zero scratch
__global__ void k_zero(int N) {
    int i = blockIdx.x * blockDim.x + threadIdx.x;
    int stride = gridDim.x * blockDim.x;
    int tot4 = N * (FDIM / 4);
    float4 z = make_float4(0.f, 0.f, 0.f, 0.f);
    for (int idx = i; idx < tot4; idx += stride) {
        reinterpret_cast<float4*>(g_min)[idx] = z;
        reinterpret_cast<float4*>(g_mout)[idx] = z;
    }
    for (int idx = i; idx < N; idx += stride) {
        g_ideg[idx] = 0.f;
        g_odeg[idx] = 0.f;
    }
}

// ---------------------------------------------------------------- degrees
__global__ void k_deg(const float* __restrict__ counts, const int* __restrict__ src,
                      const int* __restrict__ dst, int E) {
    int e = blockIdx.x * blockDim.x + threadIdx.x;
    if (e < E) {
        float c = counts[e];
        atomicAdd(&g_ideg[dst[e]], c);
        atomicAdd(&g_odeg[src[e]], c);
    }
}

// ---------------------------------------------------------------- fused node GEMMs
// h_s2d = x@Ws2d + bs2d ; h_d2s = x@Wd2s + bd2s ;
// u = x@Wl1[0:64] + bl1 ; v = x@Wl1[64:128]
// blockDim (16,16): tx = j-quad (4 output cols via float4), ty = node in 16-tile.
// Each block covers 64 nodes (4 sub-tiles). Weights in dyn smem (70,464 B).
__global__ __launch_bounds__(256) void k_node_pre(
    const float* __restrict__ x,
    const float* __restrict__ Ws2d, const float* __restrict__ bs2d,
    const float* __restrict__ Wd2s, const float* __restrict__ bd2s,
    const float* __restrict__ Wl1,  const float* __restrict__ bl1,
    int N)
{
    extern __shared__ float sm[];
    float* sWs = sm;            // 4096
    float* sWd = sm + 4096;     // 4096
    float* sW1 = sm + 8192;     // 8192 (rows 0..127)
    float* sb  = sm + 16384;    // 192
    float* sx  = sm + 16576;    // 16*65 (padded stride: bank-conflict-free broadcast)

    int tx = threadIdx.x, ty = threadIdx.y;
    int tid = ty * 16 + tx;
    for (int i = tid; i < 4096; i += 256) { sWs[i] = Ws2d[i]; sWd[i] = Wd2s[i]; }
    for (int i = tid; i < 8192; i += 256) { sW1[i] = Wl1[i]; }
    if (tid < 64) { sb[tid] = bs2d[tid]; sb[64 + tid] = bd2s[tid]; sb[128 + tid] = bl1[tid]; }

    int j0 = 4 * tx;
    for (int it = 0; it < 4; ++it) {
        int n0 = blockIdx.x * 64 + it * 16;
        __syncthreads();  // W-load done (it=0) / prev compute done before sx overwrite
        for (int i = tid; i < 16 * FDIM; i += 256) {
            int r = i >> 6, c = i & 63;
            int n = n0 + r;
            sx[r * 65 + c] = (n < N) ? x[n * FDIM + c] : 0.f;
        }
        __syncthreads();

        float4 ahs = make_float4(0.f, 0.f, 0.f, 0.f);
        float4 ahd = ahs, au = ahs, av = ahs;
        const float* xr = &sx[ty * 65];
#pragma unroll 8
        for (int k = 0; k < FDIM; k++) {
            float xv = xr[k];
            float4 w;
            w = *reinterpret_cast<const float4*>(&sWs[k * 64 + j0]);
            ahs.x += xv * w.x; ahs.y += xv * w.y; ahs.z += xv * w.z; ahs.w += xv * w.w;
            w = *reinterpret_cast<const float4*>(&sWd[k * 64 + j0]);
            ahd.x += xv * w.x; ahd.y += xv * w.y; ahd.z += xv * w.z; ahd.w += xv * w.w;
            w = *reinterpret_cast<const float4*>(&sW1[k * 64 + j0]);
            au.x  += xv * w.x; au.y  += xv * w.y; au.z  += xv * w.z; au.w  += xv * w.w;
            w = *reinterpret_cast<const float4*>(&sW1[(k + 64) * 64 + j0]);
            av.x  += xv * w.x; av.y  += xv * w.y; av.z  += xv * w.z; av.w  += xv * w.w;
        }

        int n = n0 + ty;
        if (n < N) {
            ahs.x += sb[j0];       ahs.y += sb[j0 + 1];       ahs.z += sb[j0 + 2];       ahs.w += sb[j0 + 3];
            ahd.x += sb[64 + j0];  ahd.y += sb[64 + j0 + 1];  ahd.z += sb[64 + j0 + 2];  ahd.w += sb[64 + j0 + 3];
            au.x  += sb[128 + j0]; au.y  += sb[128 + j0 + 1]; au.z  += sb[128 + j0 + 2]; au.w  += sb[128 + j0 + 3];
            *reinterpret_cast<float4*>(&g_hs[n * FDIM + j0]) = ahs;
            *reinterpret_cast<float4*>(&g_hd[n * FDIM + j0]) = ahd;
            *reinterpret_cast<float4*>(&g_u[n * FDIM + j0])  = au;
            *reinterpret_cast<float4*>(&g_v[n * FDIM + j0])  = av;
        }
    }
}

// ---------------------------------------------------------------- edge kernel (warp/edge)
// z = sum_j relu(u[src][j] + v[dst][j]) * Wl2[j] + bl2 ; keep iff z >= 0
// w = counts * rsqrt(max(odeg[src],1) * max(ideg[dst],1))
// m_in[dst]  += w * h_s2d[src] ; m_out[src] += w * h_d2s[dst]   (red.v2)
__global__ __launch_bounds__(256) void k_edge(
    const float* __restrict__ counts, const int* __restrict__ src,
    const int* __restrict__ dst, const float* __restrict__ Wl2,
    const float* __restrict__ bl2, int E)
{
    int lane = threadIdx.x & 31;
    int e = (blockIdx.x * blockDim.x + threadIdx.x) >> 5;
    if (e >= E) return;

    int s = src[e];
    int d = dst[e];

    float2 uu = reinterpret_cast<const float2*>(g_u)[s * 32 + lane];
    float2 vv = reinterpret_cast<const float2*>(g_v)[d * 32 + lane];
    float hx = fmaxf(uu.x + vv.x, 0.f);
    float hy = fmaxf(uu.y + vv.y, 0.f);
    float2 w2 = reinterpret_cast<const float2*>(Wl2)[lane];
    float z = hx * w2.x + hy * w2.y;
#pragma unroll
    for (int off = 16; off; off >>= 1) z += __shfl_xor_sync(0xffffffffu, z, off);
    if (z + bl2[0] < 0.f) return;   // keep = sigmoid(z) >= 0.5  <=>  z >= 0

    float w = counts[e] * rsqrtf(fmaxf(g_odeg[s], 1.f) * fmaxf(g_ideg[d], 1.f));
    float2 hs = reinterpret_cast<const float2*>(g_hs)[s * 32 + lane];
    float2 hd = reinterpret_cast<const float2*>(g_hd)[d * 32 + lane];
    red2(&g_min[d * FDIM + 2 * lane],  w * hs.x, w * hs.y);
    red2(&g_mout[s * FDIM + 2 * lane], w * hd.x, w * hd.y);
}

// ---------------------------------------------------------------- gate + blend + residual (warp/node)
__global__ __launch_bounds__(256) void k_gate(
    const float* __restrict__ x,
    const float* __restrict__ Wg1, const float* __restrict__ bg1,
    const float* __restrict__ Wg2, const float* __restrict__ bg2,
    float* __restrict__ out, int N)
{
    __shared__ __align__(16) float sW[128 * 64];
    __shared__ __align__(16) float sb1[64];
    __shared__ __align__(16) float sw2[64];
    __shared__ __align__(16) float scat[8][128];

    int tid = threadIdx.x;
    for (int i = tid; i < 8192; i += 256) sW[i] = Wg1[i];
    if (tid < 64) { sb1[tid] = bg1[tid]; sw2[tid] = Wg2[tid]; }
    __syncthreads();

    int lane = tid & 31, wp = tid >> 5;
    float bg2v = bg2[0];

    for (int n = blockIdx.x * 8 + wp; n < N; n += gridDim.x * 8) {
        float2 mi = reinterpret_cast<const float2*>(g_min)[n * 32 + lane];
        float2 mo = reinterpret_cast<const float2*>(g_mout)[n * 32 + lane];
        scat[wp][2 * lane] = mi.x;      scat[wp][2 * lane + 1] = mi.y;
        scat[wp][64 + 2 * lane] = mo.x; scat[wp][64 + 2 * lane + 1] = mo.y;
        __syncwarp();

        float a0 = sb1[2 * lane], a1 = sb1[2 * lane + 1];
#pragma unroll 8
        for (int k = 0; k < 128; k++) {
            float xv = scat[wp][k];
            float2 wv = reinterpret_cast<const float2*>(sW)[k * 32 + lane];
            a0 += xv * wv.x;
            a1 += xv * wv.y;
        }
        a0 = fmaxf(a0, 0.f);
        a1 = fmaxf(a1, 0.f);
        float z = a0 * sw2[2 * lane] + a1 * sw2[2 * lane + 1];
#pragma unroll
        for (int off = 16; off; off >>= 1) z += __shfl_xor_sync(0xffffffffu, z, off);

        float gate = 1.f / (1.f + __expf(-(z + bg2v)));
        float ga = 0.5f * gate;        // ALPHA * gate
        float gb = 0.5f - ga;          // (1-ALPHA) * (1-gate)
        float2 xr = reinterpret_cast<const float2*>(x)[n * 32 + lane];
        float2 o;
        o.x = ga * mi.x + gb * mo.x + xr.x;
        o.y = ga * mi.y + gb * mo.y + xr.y;
        reinterpret_cast<float2*>(out)[n * 32 + lane] = o;
        __syncwarp();   // protect scat row before next iteration's writes
    }
}

// ---------------------------------------------------------------- launch
extern "C" void kernel_launch(void* const* d_in, const int* in_sizes, int n_in,
                              void* d_out, int out_size) {
    const float* x      = (const float*)d_in[0];
    const float* counts = (const float*)d_in[1];
    const float* Ws2d   = (const float*)d_in[2];
    const float* bs2d   = (const float*)d_in[3];
    const float* Wd2s   = (const float*)d_in[4];
    const float* bd2s   = (const float*)d_in[5];
    const float* Wl1    = (const float*)d_in[6];
    const float* bl1    = (const float*)d_in[7];
    const float* Wl2    = (const float*)d_in[8];
    const float* bl2    = (const float*)d_in[9];
    const float* Wg1    = (const float*)d_in[10];
    const float* bg1    = (const float*)d_in[11];
    const float* Wg2    = (const float*)d_in[12];
    const float* bg2    = (const float*)d_in[13];
    const int*   src    = (const int*)d_in[14];
    const int*   dst    = (const int*)d_in[15];
    float* out = (float*)d_out;

    int N = in_sizes[0] / FDIM;
    int E = in_sizes[1];

    k_zero<<<1024, 256>>>(N);
    k_deg<<<(E + 255) / 256, 256>>>(counts, src, dst, E);

    cudaFuncSetAttribute(k_node_pre, cudaFuncAttributeMaxDynamicSharedMemorySize, 70464);
    dim3 bpre(16, 16);
    k_node_pre<<<(N + 63) / 64, bpre, 70464>>>(x, Ws2d, bs2d, Wd2s, bd2s, Wl1, bl1, N);

    int edge_blocks = (E * 32 + 255) / 256;
    k_edge<<<edge_blocks, 256>>>(counts, src, dst, Wl2, bl2, E);

    k_gate<<<1184, 256>>>(x, Wg1, bg1, Wg2, bg2, out, N);
}

// round 6
// speedup vs baseline: 1.2333x; 1.2333x over previous
#include <cuda_runtime.h>

#define FDIM 64
#define NMAX 50176

// Scratch (allocation-free rule: __device__ globals)
__device__ __align__(16) float g_u[NMAX * FDIM];
__device__ __align__(16) float g_v[NMAX * FDIM];
__device__ __align__(16) float g_hs[NMAX * FDIM];
__device__ __align__(16) float g_hd[NMAX * FDIM];
__device__ __align__(16) float g_min[NMAX * FDIM];
__device__ __align__(16) float g_mout[NMAX * FDIM];
__device__ __align__(16) float g_ideg[NMAX];
__device__ __align__(16) float g_odeg[NMAX];

__device__ __forceinline__ void red4(float* p, float a, float b, float c, float d) {
    asm volatile("red.global.add.v4.f32 [%0], {%1, %2, %3, %4};"
                 :: "l"(__cvta_generic_to_global(p)), "f"(a), "f"(b), "f"(c), "f"(d)
                 : "memory");
}

// ---------------------------------------------------------------- zero scratch
__global__ void k_zero(int N) {
    int i = blockIdx.x * blockDim.x + threadIdx.x;
    int stride = gridDim.x * blockDim.x;
    int tot4 = N * (FDIM / 4);
    float4 z = make_float4(0.f, 0.f, 0.f, 0.f);
    for (int idx = i; idx < tot4; idx += stride) {
        reinterpret_cast<float4*>(g_min)[idx] = z;
        reinterpret_cast<float4*>(g_mout)[idx] = z;
    }
    for (int idx = i; idx < N; idx += stride) {
        g_ideg[idx] = 0.f;
        g_odeg[idx] = 0.f;
    }
}

// ---------------------------------------------------------------- degrees
__global__ void k_deg(const float* __restrict__ counts, const int* __restrict__ src,
                      const int* __restrict__ dst, int E) {
    int e = blockIdx.x * blockDim.x + threadIdx.x;
    if (e < E) {
        float c = __ldg(&counts[e]);
        atomicAdd(&g_ideg[__ldg(&dst[e])], c);
        atomicAdd(&g_odeg[__ldg(&src[e])], c);
    }
}

// ---------------------------------------------------------------- fused node GEMMs
// h_s2d = x@Ws2d + bs2d ; h_d2s = x@Wd2s + bd2s ;
// u = x@Wl1[0:64] + bl1 ; v = x@Wl1[64:128]
// blockDim (16,16): tx = j-quad (4 cols via float4), ty + 16r = node (r=0..3).
// 4-node register tiling: each weight float4 read once per 4 nodes.
__global__ __launch_bounds__(256) void k_node_pre(
    const float* __restrict__ x,
    const float* __restrict__ Ws2d, const float* __restrict__ bs2d,
    const float* __restrict__ Wd2s, const float* __restrict__ bd2s,
    const float* __restrict__ Wl1,  const float* __restrict__ bl1,
    int N)
{
    extern __shared__ float sm[];
    float* sWs = sm;            // 4096
    float* sWd = sm + 4096;     // 4096
    float* sW1 = sm + 8192;     // 8192 (rows 0..127)
    float* sb  = sm + 16384;    // 192
    float* sx  = sm + 16576;    // 64*65 (padded stride)

    int tx = threadIdx.x, ty = threadIdx.y;
    int tid = ty * 16 + tx;
    for (int i = tid; i < 4096; i += 256) { sWs[i] = Ws2d[i]; sWd[i] = Wd2s[i]; }
    for (int i = tid; i < 8192; i += 256) { sW1[i] = Wl1[i]; }
    if (tid < 64) { sb[tid] = bs2d[tid]; sb[64 + tid] = bd2s[tid]; sb[128 + tid] = bl1[tid]; }

    int nbase = blockIdx.x * 64;
    for (int i = tid; i < 64 * FDIM; i += 256) {
        int r = i >> 6, c = i & 63;
        int n = nbase + r;
        sx[r * 65 + c] = (n < N) ? x[n * FDIM + c] : 0.f;
    }
    __syncthreads();

    int j0 = 4 * tx;
    float4 ahs[4], ahd[4], au[4], av[4];
#pragma unroll
    for (int r = 0; r < 4; r++) {
        ahs[r] = make_float4(0.f, 0.f, 0.f, 0.f);
        ahd[r] = ahs[r]; au[r] = ahs[r]; av[r] = ahs[r];
    }

#pragma unroll 2
    for (int k = 0; k < FDIM; k++) {
        float4 ws = *reinterpret_cast<const float4*>(&sWs[k * 64 + j0]);
        float4 wd = *reinterpret_cast<const float4*>(&sWd[k * 64 + j0]);
        float4 wa = *reinterpret_cast<const float4*>(&sW1[k * 64 + j0]);
        float4 wb = *reinterpret_cast<const float4*>(&sW1[(k + 64) * 64 + j0]);
#pragma unroll
        for (int r = 0; r < 4; r++) {
            float xv = sx[(ty + 16 * r) * 65 + k];
            ahs[r].x += xv * ws.x; ahs[r].y += xv * ws.y; ahs[r].z += xv * ws.z; ahs[r].w += xv * ws.w;
            ahd[r].x += xv * wd.x; ahd[r].y += xv * wd.y; ahd[r].z += xv * wd.z; ahd[r].w += xv * wd.w;
            au[r].x  += xv * wa.x; au[r].y  += xv * wa.y; au[r].z  += xv * wa.z; au[r].w  += xv * wa.w;
            av[r].x  += xv * wb.x; av[r].y  += xv * wb.y; av[r].z  += xv * wb.z; av[r].w  += xv * wb.w;
        }
    }

#pragma unroll
    for (int r = 0; r < 4; r++) {
        int n = nbase + ty + 16 * r;
        if (n < N) {
            ahs[r].x += sb[j0];       ahs[r].y += sb[j0 + 1];       ahs[r].z += sb[j0 + 2];       ahs[r].w += sb[j0 + 3];
            ahd[r].x += sb[64 + j0];  ahd[r].y += sb[64 + j0 + 1];  ahd[r].z += sb[64 + j0 + 2];  ahd[r].w += sb[64 + j0 + 3];
            au[r].x  += sb[128 + j0]; au[r].y  += sb[128 + j0 + 1]; au[r].z  += sb[128 + j0 + 2]; au[r].w  += sb[128 + j0 + 3];
            *reinterpret_cast<float4*>(&g_hs[n * FDIM + j0]) = ahs[r];
            *reinterpret_cast<float4*>(&g_hd[n * FDIM + j0]) = ahd[r];
            *reinterpret_cast<float4*>(&g_u[n * FDIM + j0])  = au[r];
            *reinterpret_cast<float4*>(&g_v[n * FDIM + j0])  = av[r];
        }
    }
}

// ---------------------------------------------------------------- edge kernel (warp/edge, 128-bit)
// lanes 0-15: src-side quad q=lane; lanes 16-31: dst-side quad q=lane-16.
// z = sum_j relu(u[src][j] + v[dst][j]) * Wl2[j] + bl2 ; keep iff z >= 0
// m_in[dst] += w*h_s2d[src] (lanes 0-15, red.v4) ; m_out[src] += w*h_d2s[dst] (lanes 16-31)
__global__ __launch_bounds__(256) void k_edge(
    const float* __restrict__ counts, const int* __restrict__ src,
    const int* __restrict__ dst, const float* __restrict__ Wl2,
    const float* __restrict__ bl2, int E)
{
    int lane = threadIdx.x & 31;
    int e = (blockIdx.x * blockDim.x + threadIdx.x) >> 5;
    if (e >= E) return;

    int s = __ldg(&src[e]);
    int d = __ldg(&dst[e]);
    int half = lane >> 4;
    int q = lane & 15;

    const float4* ub = reinterpret_cast<const float4*>(g_u) + (size_t)s * 16;
    const float4* vb = reinterpret_cast<const float4*>(g_v) + (size_t)d * 16;
    float4 a = half ? vb[q] : ub[q];
    float4 b;
    b.x = __shfl_xor_sync(0xffffffffu, a.x, 16);
    b.y = __shfl_xor_sync(0xffffffffu, a.y, 16);
    b.z = __shfl_xor_sync(0xffffffffu, a.z, 16);
    b.w = __shfl_xor_sync(0xffffffffu, a.w, 16);

    float4 w2 = __ldg(reinterpret_cast<const float4*>(Wl2) + q);
    float z = fmaxf(a.x + b.x, 0.f) * w2.x + fmaxf(a.y + b.y, 0.f) * w2.y
            + fmaxf(a.z + b.z, 0.f) * w2.z + fmaxf(a.w + b.w, 0.f) * w2.w;
#pragma unroll
    for (int off = 8; off; off >>= 1) z += __shfl_xor_sync(0xffffffffu, z, off);
    if (z + __ldg(bl2) < 0.f) return;   // keep = sigmoid(z) >= 0.5  <=>  z >= 0

    float w = __ldg(&counts[e]) * rsqrtf(fmaxf(g_odeg[s], 1.f) * fmaxf(g_ideg[d], 1.f));
    const float4* hb = half ? reinterpret_cast<const float4*>(g_hd) + (size_t)d * 16
                            : reinterpret_cast<const float4*>(g_hs) + (size_t)s * 16;
    float4 h = hb[q];
    float* tgt = half ? &g_mout[s * FDIM + 4 * q] : &g_min[d * FDIM + 4 * q];
    red4(tgt, w * h.x, w * h.y, w * h.z, w * h.w);
}

// ---------------------------------------------------------------- gate + blend + residual
// warp handles 4 nodes: weight float2 read once per 4 nodes.
__global__ __launch_bounds__(256) void k_gate(
    const float* __restrict__ x,
    const float* __restrict__ Wg1, const float* __restrict__ bg1,
    const float* __restrict__ Wg2, const float* __restrict__ bg2,
    float* __restrict__ out, int N)
{
    extern __shared__ float gsm[];
    float* sW   = gsm;          // 8192
    float* sb1  = gsm + 8192;   // 64
    float* sw2  = gsm + 8256;   // 64
    float* scat = gsm + 8320;   // 8 warps * 4 nodes * 128

    int tid = threadIdx.x;
    for (int i = tid; i < 8192; i += 256) sW[i] = Wg1[i];
    if (tid < 64) { sb1[tid] = bg1[tid]; sw2[tid] = Wg2[tid]; }
    __syncthreads();

    int lane = tid & 31, wp = tid >> 5;
    float bg2v = bg2[0];
    float* row = scat + wp * 512;

    for (int base = (blockIdx.x * 8 + wp) * 4; base < N; base += gridDim.x * 32) {
        float2 mi[4], mo[4];
#pragma unroll
        for (int r = 0; r < 4; r++) {
            int n = base + r;
            int nc = (n < N) ? n : (N - 1);
            mi[r] = reinterpret_cast<const float2*>(g_min)[nc * 32 + lane];
            mo[r] = reinterpret_cast<const float2*>(g_mout)[nc * 32 + lane];
            row[r * 128 + 2 * lane] = mi[r].x;      row[r * 128 + 2 * lane + 1] = mi[r].y;
            row[r * 128 + 64 + 2 * lane] = mo[r].x; row[r * 128 + 64 + 2 * lane + 1] = mo[r].y;
        }
        __syncwarp();

        float a0[4], a1[4];
#pragma unroll
        for (int r = 0; r < 4; r++) { a0[r] = sb1[2 * lane]; a1[r] = sb1[2 * lane + 1]; }

#pragma unroll 4
        for (int k = 0; k < 128; k++) {
            float2 wv = reinterpret_cast<const float2*>(sW)[k * 32 + lane];
#pragma unroll
            for (int r = 0; r < 4; r++) {
                float xv = row[r * 128 + k];
                a0[r] += xv * wv.x;
                a1[r] += xv * wv.y;
            }
        }

        float zr[4];
#pragma unroll
        for (int r = 0; r < 4; r++) {
            float h0 = fmaxf(a0[r], 0.f), h1 = fmaxf(a1[r], 0.f);
            zr[r] = h0 * sw2[2 * lane] + h1 * sw2[2 * lane + 1];
        }
#pragma unroll
        for (int off = 16; off; off >>= 1) {
#pragma unroll
            for (int r = 0; r < 4; r++) zr[r] += __shfl_xor_sync(0xffffffffu, zr[r], off);
        }

#pragma unroll
        for (int r = 0; r < 4; r++) {
            int n = base + r;
            if (n < N) {
                float gate = 1.f / (1.f + __expf(-(zr[r] + bg2v)));
                float ga = 0.5f * gate;        // ALPHA * gate
                float gb = 0.5f - ga;          // (1-ALPHA) * (1-gate)
                float2 xr = reinterpret_cast<const float2*>(x)[n * 32 + lane];
                float2 o;
                o.x = ga * mi[r].x + gb * mo[r].x + xr.x;
                o.y = ga * mi[r].y + gb * mo[r].y + xr.y;
                reinterpret_cast<float2*>(out)[n * 32 + lane] = o;
            }
        }
        __syncwarp();
    }
}

// ---------------------------------------------------------------- launch
extern "C" void kernel_launch(void* const* d_in, const int* in_sizes, int n_in,
                              void* d_out, int out_size) {
    const float* x      = (const float*)d_in[0];
    const float* counts = (const float*)d_in[1];
    const float* Ws2d   = (const float*)d_in[2];
    const float* bs2d   = (const float*)d_in[3];
    const float* Wd2s   = (const float*)d_in[4];
    const float* bd2s   = (const float*)d_in[5];
    const float* Wl1    = (const float*)d_in[6];
    const float* bl1    = (const float*)d_in[7];
    const float* Wl2    = (const float*)d_in[8];
    const float* bl2    = (const float*)d_in[9];
    const float* Wg1    = (const float*)d_in[10];
    const float* bg1    = (const float*)d_in[11];
    const float* Wg2    = (const float*)d_in[12];
    const float* bg2    = (const float*)d_in[13];
    const int*   src    = (const int*)d_in[14];
    const int*   dst    = (const int*)d_in[15];
    float* out = (float*)d_out;

    int N = in_sizes[0] / FDIM;
    int E = in_sizes[1];

    // Deterministic every call (no static guards — harness rule).
    cudaFuncSetAttribute(k_node_pre, cudaFuncAttributeMaxDynamicSharedMemorySize, 82944);
    cudaFuncSetAttribute(k_gate, cudaFuncAttributeMaxDynamicSharedMemorySize, 49664);

    k_zero<<<1024, 256>>>(N);
    k_deg<<<(E + 255) / 256, 256>>>(counts, src, dst, E);

    dim3 bpre(16, 16);
    k_node_pre<<<(N + 63) / 64, bpre, 82944>>>(x, Ws2d, bs2d, Wd2s, bd2s, Wl1, bl1, N);

    int edge_blocks = (E * 32 + 255) / 256;
    k_edge<<<edge_blocks, 256>>>(counts, src, dst, Wl2, bl2, E);

    k_gate<<<(N + 31) / 32, 256, 49664>>>(x, Wg1, bg1, Wg2, bg2, out, N);
}

// round 7
// speedup vs baseline: 1.4440x; 1.1708x over previous
#include <cuda_runtime.h>

#define FDIM 64
#define NMAX 50176

// Scratch (allocation-free rule: __device__ globals)
__device__ __align__(16) float g_u[NMAX * FDIM];
__device__ __align__(16) float g_v[NMAX * FDIM];
__device__ __align__(16) float g_hs[NMAX * FDIM];
__device__ __align__(16) float g_hd[NMAX * FDIM];
__device__ __align__(16) float g_min[NMAX * FDIM];
__device__ __align__(16) float g_mout[NMAX * FDIM];
__device__ __align__(16) float g_ideg[NMAX];
__device__ __align__(16) float g_odeg[NMAX];

__device__ __forceinline__ void red4(float* p, float a, float b, float c, float d) {
    asm volatile("red.global.add.v4.f32 [%0], {%1, %2, %3, %4};"
                 :: "l"(__cvta_generic_to_global(p)), "f"(a), "f"(b), "f"(c), "f"(d)
                 : "memory");
}

// ---------------------------------------------------------------- zero scratch
__global__ void k_zero(int N) {
    int i = blockIdx.x * blockDim.x + threadIdx.x;
    int stride = gridDim.x * blockDim.x;
    int tot4 = N * (FDIM / 4);
    float4 z = make_float4(0.f, 0.f, 0.f, 0.f);
    for (int idx = i; idx < tot4; idx += stride) {
        reinterpret_cast<float4*>(g_min)[idx] = z;
        reinterpret_cast<float4*>(g_mout)[idx] = z;
    }
    for (int idx = i; idx < N; idx += stride) {
        g_ideg[idx] = 0.f;
        g_odeg[idx] = 0.f;
    }
}

// ---------------------------------------------------------------- degrees
__global__ void k_deg(const float* __restrict__ counts, const int* __restrict__ src,
                      const int* __restrict__ dst, int E) {
    int e = blockIdx.x * blockDim.x + threadIdx.x;
    if (e < E) {
        float c = __ldg(&counts[e]);
        atomicAdd(&g_ideg[__ldg(&dst[e])], c);
        atomicAdd(&g_odeg[__ldg(&src[e])], c);
    }
}

// ---------------------------------------------------------------- fused node GEMMs
// h_s2d = x@Ws2d + bs2d ; h_d2s = x@Wd2s + bd2s ;
// u = x@Wl1[0:64] + bl1 ; v = x@Wl1[64:128]
__global__ __launch_bounds__(256) void k_node_pre(
    const float* __restrict__ x,
    const float* __restrict__ Ws2d, const float* __restrict__ bs2d,
    const float* __restrict__ Wd2s, const float* __restrict__ bd2s,
    const float* __restrict__ Wl1,  const float* __restrict__ bl1,
    int N)
{
    extern __shared__ float sm[];
    float* sWs = sm;            // 4096
    float* sWd = sm + 4096;     // 4096
    float* sW1 = sm + 8192;     // 8192 (rows 0..127)
    float* sb  = sm + 16384;    // 192
    float* sx  = sm + 16576;    // 64*65 (padded stride)

    int tx = threadIdx.x, ty = threadIdx.y;
    int tid = ty * 16 + tx;
    for (int i = tid; i < 4096; i += 256) { sWs[i] = Ws2d[i]; sWd[i] = Wd2s[i]; }
    for (int i = tid; i < 8192; i += 256) { sW1[i] = Wl1[i]; }
    if (tid < 64) { sb[tid] = bs2d[tid]; sb[64 + tid] = bd2s[tid]; sb[128 + tid] = bl1[tid]; }

    int nbase = blockIdx.x * 64;
    for (int i = tid; i < 64 * FDIM; i += 256) {
        int r = i >> 6, c = i & 63;
        int n = nbase + r;
        sx[r * 65 + c] = (n < N) ? x[n * FDIM + c] : 0.f;
    }
    __syncthreads();

    int j0 = 4 * tx;
    float4 ahs[4], ahd[4], au[4], av[4];
#pragma unroll
    for (int r = 0; r < 4; r++) {
        ahs[r] = make_float4(0.f, 0.f, 0.f, 0.f);
        ahd[r] = ahs[r]; au[r] = ahs[r]; av[r] = ahs[r];
    }

#pragma unroll 2
    for (int k = 0; k < FDIM; k++) {
        float4 ws = *reinterpret_cast<const float4*>(&sWs[k * 64 + j0]);
        float4 wd = *reinterpret_cast<const float4*>(&sWd[k * 64 + j0]);
        float4 wa = *reinterpret_cast<const float4*>(&sW1[k * 64 + j0]);
        float4 wb = *reinterpret_cast<const float4*>(&sW1[(k + 64) * 64 + j0]);
#pragma unroll
        for (int r = 0; r < 4; r++) {
            float xv = sx[(ty + 16 * r) * 65 + k];
            ahs[r].x += xv * ws.x; ahs[r].y += xv * ws.y; ahs[r].z += xv * ws.z; ahs[r].w += xv * ws.w;
            ahd[r].x += xv * wd.x; ahd[r].y += xv * wd.y; ahd[r].z += xv * wd.z; ahd[r].w += xv * wd.w;
            au[r].x  += xv * wa.x; au[r].y  += xv * wa.y; au[r].z  += xv * wa.z; au[r].w  += xv * wa.w;
            av[r].x  += xv * wb.x; av[r].y  += xv * wb.y; av[r].z  += xv * wb.z; av[r].w  += xv * wb.w;
        }
    }

#pragma unroll
    for (int r = 0; r < 4; r++) {
        int n = nbase + ty + 16 * r;
        if (n < N) {
            ahs[r].x += sb[j0];       ahs[r].y += sb[j0 + 1];       ahs[r].z += sb[j0 + 2];       ahs[r].w += sb[j0 + 3];
            ahd[r].x += sb[64 + j0];  ahd[r].y += sb[64 + j0 + 1];  ahd[r].z += sb[64 + j0 + 2];  ahd[r].w += sb[64 + j0 + 3];
            au[r].x  += sb[128 + j0]; au[r].y  += sb[128 + j0 + 1]; au[r].z  += sb[128 + j0 + 2]; au[r].w  += sb[128 + j0 + 3];
            *reinterpret_cast<float4*>(&g_hs[n * FDIM + j0]) = ahs[r];
            *reinterpret_cast<float4*>(&g_hd[n * FDIM + j0]) = ahd[r];
            *reinterpret_cast<float4*>(&g_u[n * FDIM + j0])  = au[r];
            *reinterpret_cast<float4*>(&g_v[n * FDIM + j0])  = av[r];
        }
    }
}

// ---------------------------------------------------------------- edge kernel
// 2 edges per warp; all gathers (u/v AND h) issued up front for max MLP.
// Per edge: lanes 0-15 handle src-side quad q, lanes 16-31 dst-side quad q.
// z = sum_j relu(u[src][j] + v[dst][j]) * Wl2[j] + bl2 ; keep iff z >= 0
// m_in[dst] += w*h_s2d[src] (lanes 0-15) ; m_out[src] += w*h_d2s[dst] (lanes 16-31)
__global__ __launch_bounds__(256) void k_edge(
    const float* __restrict__ counts, const int* __restrict__ src,
    const int* __restrict__ dst, const float* __restrict__ Wl2,
    const float* __restrict__ bl2, int E)
{
    int lane = threadIdx.x & 31;
    int wid = (blockIdx.x * blockDim.x + threadIdx.x) >> 5;
    int e0 = wid * 2;
    if (e0 >= E) return;
    int e1 = e0 + 1;
    bool has1 = (e1 < E);
    int e1c = has1 ? e1 : e0;

    int half = lane >> 4;
    int q = lane & 15;

    int s0 = __ldg(&src[e0]), d0 = __ldg(&dst[e0]);
    int s1 = __ldg(&src[e1c]), d1 = __ldg(&dst[e1c]);

    int n0 = half ? d0 : s0;          // node whose row this half reads
    int n1 = half ? d1 : s1;
    const float4* uvb = reinterpret_cast<const float4*>(half ? g_v : g_u);
    const float4* hb  = reinterpret_cast<const float4*>(half ? g_hd : g_hs);

    // ---- batched independent gathers (8 row-LDG.128 across the warp pair) ----
    float4 a0 = __ldg(uvb + (size_t)n0 * 16 + q);
    float4 a1 = __ldg(uvb + (size_t)n1 * 16 + q);
    float4 h0 = __ldg(hb  + (size_t)n0 * 16 + q);
    float4 h1 = __ldg(hb  + (size_t)n1 * 16 + q);
    float4 w2 = __ldg(reinterpret_cast<const float4*>(Wl2) + q);
    float c0 = __ldg(&counts[e0]);
    float c1 = __ldg(&counts[e1c]);
    float od0 = __ldg(&g_odeg[s0]), id0 = __ldg(&g_ideg[d0]);
    float od1 = __ldg(&g_odeg[s1]), id1 = __ldg(&g_ideg[d1]);
    float blv = __ldg(bl2);

    // ---- exchange halves: each lane gets the partner row's quad ----
    float4 b0, b1;
    b0.x = __shfl_xor_sync(0xffffffffu, a0.x, 16);
    b0.y = __shfl_xor_sync(0xffffffffu, a0.y, 16);
    b0.z = __shfl_xor_sync(0xffffffffu, a0.z, 16);
    b0.w = __shfl_xor_sync(0xffffffffu, a0.w, 16);
    b1.x = __shfl_xor_sync(0xffffffffu, a1.x, 16);
    b1.y = __shfl_xor_sync(0xffffffffu, a1.y, 16);
    b1.z = __shfl_xor_sync(0xffffffffu, a1.z, 16);
    b1.w = __shfl_xor_sync(0xffffffffu, a1.w, 16);

    float z0 = fmaxf(a0.x + b0.x, 0.f) * w2.x + fmaxf(a0.y + b0.y, 0.f) * w2.y
             + fmaxf(a0.z + b0.z, 0.f) * w2.z + fmaxf(a0.w + b0.w, 0.f) * w2.w;
    float z1 = fmaxf(a1.x + b1.x, 0.f) * w2.x + fmaxf(a1.y + b1.y, 0.f) * w2.y
             + fmaxf(a1.z + b1.z, 0.f) * w2.z + fmaxf(a1.w + b1.w, 0.f) * w2.w;
#pragma unroll
    for (int off = 8; off; off >>= 1) {
        z0 += __shfl_xor_sync(0xffffffffu, z0, off);
        z1 += __shfl_xor_sync(0xffffffffu, z1, off);
    }

    // ---- conditional scatters (keep = sigmoid(z) >= 0.5 <=> z >= 0) ----
    if (z0 + blv >= 0.f) {
        float w = c0 * rsqrtf(fmaxf(od0, 1.f) * fmaxf(id0, 1.f));
        float* tgt = half ? &g_mout[s0 * FDIM + 4 * q] : &g_min[d0 * FDIM + 4 * q];
        red4(tgt, w * h0.x, w * h0.y, w * h0.z, w * h0.w);
    }
    if (has1 && z1 + blv >= 0.f) {
        float w = c1 * rsqrtf(fmaxf(od1, 1.f) * fmaxf(id1, 1.f));
        float* tgt = half ? &g_mout[s1 * FDIM + 4 * q] : &g_min[d1 * FDIM + 4 * q];
        red4(tgt, w * h1.x, w * h1.y, w * h1.z, w * h1.w);
    }
}

// ---------------------------------------------------------------- gate + blend + residual
// warp handles 4 nodes: weight float2 read once per 4 nodes.
__global__ __launch_bounds__(256) void k_gate(
    const float* __restrict__ x,
    const float* __restrict__ Wg1, const float* __restrict__ bg1,
    const float* __restrict__ Wg2, const float* __restrict__ bg2,
    float* __restrict__ out, int N)
{
    extern __shared__ float gsm[];
    float* sW   = gsm;          // 8192
    float* sb1  = gsm + 8192;   // 64
    float* sw2  = gsm + 8256;   // 64
    float* scat = gsm + 8320;   // 8 warps * 4 nodes * 128

    int tid = threadIdx.x;
    for (int i = tid; i < 8192; i += 256) sW[i] = Wg1[i];
    if (tid < 64) { sb1[tid] = bg1[tid]; sw2[tid] = Wg2[tid]; }
    __syncthreads();

    int lane = tid & 31, wp = tid >> 5;
    float bg2v = bg2[0];
    float* row = scat + wp * 512;

    for (int base = (blockIdx.x * 8 + wp) * 4; base < N; base += gridDim.x * 32) {
        float2 mi[4], mo[4];
#pragma unroll
        for (int r = 0; r < 4; r++) {
            int n = base + r;
            int nc = (n < N) ? n : (N - 1);
            mi[r] = reinterpret_cast<const float2*>(g_min)[nc * 32 + lane];
            mo[r] = reinterpret_cast<const float2*>(g_mout)[nc * 32 + lane];
            row[r * 128 + 2 * lane] = mi[r].x;      row[r * 128 + 2 * lane + 1] = mi[r].y;
            row[r * 128 + 64 + 2 * lane] = mo[r].x; row[r * 128 + 64 + 2 * lane + 1] = mo[r].y;
        }
        __syncwarp();

        float a0[4], a1[4];
#pragma unroll
        for (int r = 0; r < 4; r++) { a0[r] = sb1[2 * lane]; a1[r] = sb1[2 * lane + 1]; }

#pragma unroll 4
        for (int k = 0; k < 128; k++) {
            float2 wv = reinterpret_cast<const float2*>(sW)[k * 32 + lane];
#pragma unroll
            for (int r = 0; r < 4; r++) {
                float xv = row[r * 128 + k];
                a0[r] += xv * wv.x;
                a1[r] += xv * wv.y;
            }
        }

        float zr[4];
#pragma unroll
        for (int r = 0; r < 4; r++) {
            float h0 = fmaxf(a0[r], 0.f), h1 = fmaxf(a1[r], 0.f);
            zr[r] = h0 * sw2[2 * lane] + h1 * sw2[2 * lane + 1];
        }
#pragma unroll
        for (int off = 16; off; off >>= 1) {
#pragma unroll
            for (int r = 0; r < 4; r++) zr[r] += __shfl_xor_sync(0xffffffffu, zr[r], off);
        }

#pragma unroll
        for (int r = 0; r < 4; r++) {
            int n = base + r;
            if (n < N) {
                float gate = 1.f / (1.f + __expf(-(zr[r] + bg2v)));
                float ga = 0.5f * gate;        // ALPHA * gate
                float gb = 0.5f - ga;          // (1-ALPHA) * (1-gate)
                float2 xr = reinterpret_cast<const float2*>(x)[n * 32 + lane];
                float2 o;
                o.x = ga * mi[r].x + gb * mo[r].x + xr.x;
                o.y = ga * mi[r].y + gb * mo[r].y + xr.y;
                reinterpret_cast<float2*>(out)[n * 32 + lane] = o;
            }
        }
        __syncwarp();
    }
}

// ---------------------------------------------------------------- launch
extern "C" void kernel_launch(void* const* d_in, const int* in_sizes, int n_in,
                              void* d_out, int out_size) {
    const float* x      = (const float*)d_in[0];
    const float* counts = (const float*)d_in[1];
    const float* Ws2d   = (const float*)d_in[2];
    const float* bs2d   = (const float*)d_in[3];
    const float* Wd2s   = (const float*)d_in[4];
    const float* bd2s   = (const float*)d_in[5];
    const float* Wl1    = (const float*)d_in[6];
    const float* bl1    = (const float*)d_in[7];
    const float* Wl2    = (const float*)d_in[8];
    const float* bl2    = (const float*)d_in[9];
    const float* Wg1    = (const float*)d_in[10];
    const float* bg1    = (const float*)d_in[11];
    const float* Wg2    = (const float*)d_in[12];
    const float* bg2    = (const float*)d_in[13];
    const int*   src    = (const int*)d_in[14];
    const int*   dst    = (const int*)d_in[15];
    float* out = (float*)d_out;

    int N = in_sizes[0] / FDIM;
    int E = in_sizes[1];

    // Deterministic every call (no static guards — harness rule).
    cudaFuncSetAttribute(k_node_pre, cudaFuncAttributeMaxDynamicSharedMemorySize, 82944);
    cudaFuncSetAttribute(k_gate, cudaFuncAttributeMaxDynamicSharedMemorySize, 49664);

    k_zero<<<1024, 256>>>(N);
    k_deg<<<(E + 255) / 256, 256>>>(counts, src, dst, E);

    dim3 bpre(16, 16);
    k_node_pre<<<(N + 63) / 64, bpre, 82944>>>(x, Ws2d, bs2d, Wd2s, bd2s, Wl1, bl1, N);

    // 2 edges per warp, 8 warps per block -> 16 edges per block
    int edge_blocks = (E + 15) / 16;
    k_edge<<<edge_blocks, 256>>>(counts, src, dst, Wl2, bl2, E);

    k_gate<<<(N + 31) / 32, 256, 49664>>>(x, Wg1, bg1, Wg2, bg2, out, N);
}